// round 14
// baseline (speedup 1.0000x reference)
#include <cuda_runtime.h>
#include <cstdint>

#define HID 64
#define EXT 32
#define TN 64
#define TM 128          // edges per tile
#define MAX_NODES 50000

// ---------------------------------------------------------------------------
// Globals
// ---------------------------------------------------------------------------
__device__ float g_P[MAX_NODES * HID];        // h @ (W1a@W2a)
__device__ float g_Q[MAX_NODES * HID];        // h @ (W1c@W2a) + b12 (bias baked in)
__device__ float g_W12[HID * HID];            // W1b @ W2a (fp32)
__device__ float g_Wa2[HID * HID];
__device__ float g_Wc2[HID * HID];
__device__ float g_b12[HID];                  // b1 @ W2a + b2
// Split bf16 weights, packed as bf16x2 per k-pair: g_Bp[kp][n], kp = k/2.
// kp [0:32)=W12_hi [32:64)=W12_lo [64:80)=W2b_hi [80:96)=W2b_lo
__device__ unsigned g_Bp[96 * 64];

typedef unsigned long long u64;

// Single extern shared declaration for all kernels
extern __shared__ __align__(16) unsigned char smraw[];

// ---------------------------------------------------------------------------
// Helpers
// ---------------------------------------------------------------------------
__device__ __forceinline__ u64 pk2(float x, float y) {
    u64 r; asm("mov.b64 %0,{%1,%2};" : "=l"(r) : "f"(x), "f"(y)); return r;
}
__device__ __forceinline__ float2 up2(u64 v) {
    float2 f; asm("mov.b64 {%0,%1},%2;" : "=f"(f.x), "=f"(f.y) : "l"(v)); return f;
}
__device__ __forceinline__ void ffma2(u64& d, u64 a, u64 b) {
    asm("fma.rn.f32x2 %0,%1,%2,%0;" : "+l"(d) : "l"(a), "l"(b));
}
// bf16 hi/lo split of two floats, packed as bf16x2 words (x0 -> low half)
__device__ __forceinline__ void split2(float x0, float x1, unsigned& hi, unsigned& lo) {
    unsigned h;
    asm("cvt.rn.bf16x2.f32 %0, %1, %2;" : "=r"(h) : "f"(x1), "f"(x0));
    float h0 = __uint_as_float(h << 16);
    float h1 = __uint_as_float(h & 0xFFFF0000u);
    float l0 = x0 - h0, l1 = x1 - h1;
    unsigned l;
    asm("cvt.rn.bf16x2.f32 %0, %1, %2;" : "=r"(l) : "f"(l1), "f"(l0));
    hi = h; lo = l;
}
__device__ __forceinline__ void mma16816(float* c, uint4 a, unsigned b0, unsigned b1) {
    asm volatile(
        "mma.sync.aligned.m16n8k16.row.col.f32.bf16.bf16.f32 "
        "{%0,%1,%2,%3},{%4,%5,%6,%7},{%8,%9},{%0,%1,%2,%3};"
        : "+f"(c[0]), "+f"(c[1]), "+f"(c[2]), "+f"(c[3])
        : "r"(a.x), "r"(a.y), "r"(a.z), "r"(a.w), "r"(b0), "r"(b1));
}

// Fragment-linear A smem address for element (row r, k-pair kp).
// Frag block (mt,kt) is 32 lanes x 16B; within 16B: regs a0..a3.
__device__ __forceinline__ unsigned frag_addr(int r, int kp) {
    int mt = r >> 4, rr = r & 15;
    int kt = kp >> 3, kk = kp & 7;
    int lane = ((rr & 7) << 2) + (kk & 3);
    int reg  = (rr >> 3) + ((kk >> 2) << 1);
    return (unsigned)(((((mt * 12 + kt) << 5) + lane) << 4) + (reg << 2));
}

// ---------------------------------------------------------------------------
// Kernel 0a: fold W2a into W1 parts + bias.  grid 49 x 256
// ---------------------------------------------------------------------------
__global__ __launch_bounds__(256) void combo_kernel(
    const float* __restrict__ W1, const float* __restrict__ b1,
    const float* __restrict__ W2, const float* __restrict__ b2)
{
    __shared__ float W2s[HID * HID];
    __shared__ float rW[256];
    for (int i = threadIdx.x; i < HID * HID; i += 256) W2s[i] = W2[i];

    int b = blockIdx.x;
    if (b < 48) {
        int mat = b >> 4, rb = b & 15;
        rW[threadIdx.x] = W1[(size_t)mat * HID * HID + rb * 256 + threadIdx.x];
        __syncthreads();
        int lr = threadIdx.x >> 6, col = threadIdx.x & 63;
        float acc = 0.f;
        #pragma unroll 8
        for (int k = 0; k < HID; k++)
            acc = fmaf(rW[lr * HID + k], W2s[k * HID + col], acc);
        float* dstW = (mat == 0) ? g_Wa2 : (mat == 1) ? g_W12 : g_Wc2;
        dstW[(rb * 4 + lr) * HID + col] = acc;
    } else {
        __syncthreads();
        if (threadIdx.x < HID) {
            float acc = b2[threadIdx.x];
            #pragma unroll 8
            for (int k = 0; k < HID; k++)
                acc = fmaf(b1[k], W2s[k * HID + threadIdx.x], acc);
            g_b12[threadIdx.x] = acc;
        }
    }
}

// ---------------------------------------------------------------------------
// Kernel 0b: build split bf16x2 weight blob.  grid 12 x 256
// ---------------------------------------------------------------------------
__global__ __launch_bounds__(256) void build_B(const float* __restrict__ W2)
{
    int idx = blockIdx.x * 256 + threadIdx.x;
    if (idx < 48 * 64) {
        int kp = idx >> 6, n = idx & 63;
        float x0, x1;
        int hi_kp, lo_kp;
        if (kp < 32) {
            x0 = g_W12[(2 * kp) * HID + n];
            x1 = g_W12[(2 * kp + 1) * HID + n];
            hi_kp = kp; lo_kp = 32 + kp;
        } else {
            int ks = kp - 32;
            x0 = W2[(size_t)(HID + 2 * ks) * HID + n];
            x1 = W2[(size_t)(HID + 2 * ks + 1) * HID + n];
            hi_kp = 64 + ks; lo_kp = 80 + ks;
        }
        unsigned hi, lo;
        split2(x0, x1, hi, lo);
        g_Bp[hi_kp * 64 + n] = hi;
        g_Bp[lo_kp * 64 + n] = lo;
    }
}

// ---------------------------------------------------------------------------
// Kernel 1: per-node  P = h @ Wa2 ; Q = h @ Wc2 + b12   (FFMA2)
// ---------------------------------------------------------------------------
#define NODE_SMEM_BYTES ((4096 + 4096 + HID * TN) * 4)

__global__ __launch_bounds__(256) void node_pre(const float* __restrict__ h,
                                                int n_nodes)
{
    float* sm  = (float*)smraw;
    float* Wa  = sm;
    float* Wc  = Wa + 4096;
    float* hst = Wc + 4096;

    for (int i = threadIdx.x; i < HID * HID; i += 256) {
        Wa[i] = g_Wa2[i];
        Wc[i] = g_Wc2[i];
    }

    const int tx = threadIdx.x & 15;
    const int ty = threadIdx.x >> 4;
    const int j0 = tx * 4;
    const int r0 = ty * 4;
    const int ntiles = (n_nodes + TN - 1) / TN;

    float4 bv = *(const float4*)(g_b12 + j0);
    u64 qb0 = pk2(bv.x, bv.x), qb1 = pk2(bv.y, bv.y),
        qb2 = pk2(bv.z, bv.z), qb3 = pk2(bv.w, bv.w);

    for (int tile = blockIdx.x; tile < ntiles; tile += gridDim.x) {
        const int base = tile * TN;
        __syncthreads();
        for (int idx = threadIdx.x; idx < (HID / 4) * TN; idx += 256) {
            int cq = idx >> 6;
            int r  = idx & (TN - 1);
            int node = base + r;
            float4 v = make_float4(0.f, 0.f, 0.f, 0.f);
            if (node < n_nodes) v = *(const float4*)(h + (size_t)node * HID + cq * 4);
            hst[(cq * 4 + 0) * TN + r] = v.x;
            hst[(cq * 4 + 1) * TN + r] = v.y;
            hst[(cq * 4 + 2) * TN + r] = v.z;
            hst[(cq * 4 + 3) * TN + r] = v.w;
        }
        __syncthreads();

        u64 aP[4][2], aQ[4][2];
        #pragma unroll
        for (int j = 0; j < 4; j++) aP[j][0] = aP[j][1] = 0ULL;
        aQ[0][0] = aQ[0][1] = qb0;
        aQ[1][0] = aQ[1][1] = qb1;
        aQ[2][0] = aQ[2][1] = qb2;
        aQ[3][0] = aQ[3][1] = qb3;

        #pragma unroll 4
        for (int k = 0; k < HID; k++) {
            ulonglong2 sv = *(const ulonglong2*)(hst + k * TN + r0);
            float4 wa = *(const float4*)(Wa + k * HID + j0);
            float4 wc = *(const float4*)(Wc + k * HID + j0);
            u64 a0 = pk2(wa.x, wa.x), a1 = pk2(wa.y, wa.y),
                a2 = pk2(wa.z, wa.z), a3 = pk2(wa.w, wa.w);
            u64 c0 = pk2(wc.x, wc.x), c1 = pk2(wc.y, wc.y),
                c2 = pk2(wc.z, wc.z), c3 = pk2(wc.w, wc.w);
            ffma2(aP[0][0], a0, sv.x); ffma2(aP[0][1], a0, sv.y);
            ffma2(aP[1][0], a1, sv.x); ffma2(aP[1][1], a1, sv.y);
            ffma2(aP[2][0], a2, sv.x); ffma2(aP[2][1], a2, sv.y);
            ffma2(aP[3][0], a3, sv.x); ffma2(aP[3][1], a3, sv.y);
            ffma2(aQ[0][0], c0, sv.x); ffma2(aQ[0][1], c0, sv.y);
            ffma2(aQ[1][0], c1, sv.x); ffma2(aQ[1][1], c1, sv.y);
            ffma2(aQ[2][0], c2, sv.x); ffma2(aQ[2][1], c2, sv.y);
            ffma2(aQ[3][0], c3, sv.x); ffma2(aQ[3][1], c3, sv.y);
        }
        #pragma unroll
        for (int r = 0; r < 4; r++) {
            int node = base + r0 + r;
            if (node < n_nodes) {
                float4 p, q; float2 c;
                c = up2(aP[0][r >> 1]); p.x = (r & 1) ? c.y : c.x;
                c = up2(aP[1][r >> 1]); p.y = (r & 1) ? c.y : c.x;
                c = up2(aP[2][r >> 1]); p.z = (r & 1) ? c.y : c.x;
                c = up2(aP[3][r >> 1]); p.w = (r & 1) ? c.y : c.x;
                c = up2(aQ[0][r >> 1]); q.x = (r & 1) ? c.y : c.x;
                c = up2(aQ[1][r >> 1]); q.y = (r & 1) ? c.y : c.x;
                c = up2(aQ[2][r >> 1]); q.z = (r & 1) ? c.y : c.x;
                c = up2(aQ[3][r >> 1]); q.w = (r & 1) ? c.y : c.x;
                *(float4*)(g_P + (size_t)node * HID + j0) = p;
                *(float4*)(g_Q + (size_t)node * HID + j0) = q;
            }
        }
    }
}

// ---------------------------------------------------------------------------
// Kernel 2: per-edge via mma.sync. R9 producer + M*N warp tiling (4mt x 2nt).
//   A kt blocks: 0-3 eh_hi | 4-7 eh_lo | 8-9 ext_hi | 10-11 ext_lo
//   Per (mt, kb<4): ah x W12_hi, ah x W12_lo, al x W12_hi
//   Per (mt, kb<2): ah x W2b_hi, ah x W2b_lo, al x W2b_hi
//   out = relu( sum + P[src] + Q[dst] )
// Warp w: wm = w>>2 (mt 4wm..4wm+3), wn = w&3 (cols 16wn..16wn+15).
// ---------------------------------------------------------------------------
#define A_BYTES (8 * 12 * 32 * 16)      // 49152
#define OFF_SRC A_BYTES
#define OFF_DST (OFF_SRC + TM * 4)
#define EDGE_SMEM_BYTES (OFF_DST + TM * 4)

__global__ __launch_bounds__(256) void edge_kernel(
    const float* __restrict__ e_h,
    const float* __restrict__ ext,
    const int* __restrict__ src,
    const int* __restrict__ dst,
    float* __restrict__ out,
    int n_edges)
{
    unsigned char* A = smraw;
    int* srcs = (int*)(smraw + OFF_SRC);
    int* dsts = (int*)(smraw + OFF_DST);

    const int tid = threadIdx.x;
    const int w = tid >> 5, lane = tid & 31;
    const int wm = w >> 2;               // 0..1: mt group
    const int wn = w & 3;                // 0..3: 16-wide n slice
    const int lr = lane >> 2;            // 0..7
    const int lc = lane & 3;             // 0..3

    // ---- B fragments, deduplicated: 24 regs per nt slice, 2 slices ----
    unsigned wh0[2][4], wh1[2][4];       // W12_hi
    unsigned wl0[2][4], wl1[2][4];       // W12_lo
    unsigned vh0[2][2], vh1[2][2];       // W2b_hi
    unsigned vl0[2][2], vl1[2][2];       // W2b_lo
    #pragma unroll
    for (int j = 0; j < 2; j++) {
        int nb = wn * 16 + j * 8 + lr;
        #pragma unroll
        for (int kb = 0; kb < 4; kb++) {
            int kp = kb * 8 + lc;
            wh0[j][kb] = g_Bp[kp * 64 + nb];
            wh1[j][kb] = g_Bp[(kp + 4) * 64 + nb];
            wl0[j][kb] = g_Bp[(32 + kp) * 64 + nb];
            wl1[j][kb] = g_Bp[(32 + kp + 4) * 64 + nb];
        }
        #pragma unroll
        for (int kb = 0; kb < 2; kb++) {
            int kp = 64 + kb * 8 + lc;
            vh0[j][kb] = g_Bp[kp * 64 + nb];
            vh1[j][kb] = g_Bp[(kp + 4) * 64 + nb];
            vl0[j][kb] = g_Bp[(kp + 16) * 64 + nb];
            vl1[j][kb] = g_Bp[(kp + 16 + 4) * 64 + nb];
        }
    }

    const int ntiles = (n_edges + TM - 1) / TM;

    for (int tile = blockIdx.x; tile < ntiles; tile += gridDim.x) {
        const int base = tile * TM;
        __syncthreads();   // previous tile fully consumed before A overwrite

        // ---- stage e_h (R9 producer): hi -> kt 0-3, lo -> kt 4-7 ----
        for (int idx = tid; idx < TM * 16; idx += 256) {
            int r = idx >> 4, c4 = (idx & 15) << 2;
            int e = base + r;
            float4 v = (e < n_edges) ? *(const float4*)(e_h + (size_t)e * HID + c4)
                                     : make_float4(0.f, 0.f, 0.f, 0.f);
            unsigned h01, l01, h23, l23;
            split2(v.x, v.y, h01, l01);
            split2(v.z, v.w, h23, l23);
            int kp = c4 >> 1;
            *(unsigned*)(A + frag_addr(r, kp))          = h01;
            *(unsigned*)(A + frag_addr(r, kp + 1))      = h23;
            *(unsigned*)(A + frag_addr(r, 32 + kp))     = l01;
            *(unsigned*)(A + frag_addr(r, 32 + kp + 1)) = l23;
        }
        // ---- stage ext: hi -> kt 8-9, lo -> kt 10-11 ----
        for (int idx = tid; idx < TM * 8; idx += 256) {
            int r = idx >> 3, c4 = (idx & 7) << 2;
            int e = base + r;
            float4 v = (e < n_edges) ? *(const float4*)(ext + (size_t)e * EXT + c4)
                                     : make_float4(0.f, 0.f, 0.f, 0.f);
            unsigned h01, l01, h23, l23;
            split2(v.x, v.y, h01, l01);
            split2(v.z, v.w, h23, l23);
            int kp = c4 >> 1;
            *(unsigned*)(A + frag_addr(r, 64 + kp))     = h01;
            *(unsigned*)(A + frag_addr(r, 64 + kp + 1)) = h23;
            *(unsigned*)(A + frag_addr(r, 80 + kp))     = l01;
            *(unsigned*)(A + frag_addr(r, 80 + kp + 1)) = l23;
        }
        if (tid < TM) {
            int e = base + tid;
            srcs[tid] = (e < n_edges) ? src[e] : 0;
            dsts[tid] = (e < n_edges) ? dst[e] : 0;
        }
        __syncthreads();

        // ---- 4 m-tiles x 2 n-slices: 12 LDS.128 + 36 MMA per mt ----
        float acc[4][2][4];
        #pragma unroll
        for (int i = 0; i < 4; i++) {
            #pragma unroll
            for (int j = 0; j < 2; j++)
                acc[i][j][0] = acc[i][j][1] = acc[i][j][2] = acc[i][j][3] = 0.f;
            const int mt = wm * 4 + i;
            const uint4* Ab = (const uint4*)(A) + (mt * 12) * 32 + lane;
            #pragma unroll
            for (int kb = 0; kb < 4; kb++) {
                uint4 ah = Ab[kb * 32];
                uint4 al = Ab[(4 + kb) * 32];
                #pragma unroll
                for (int j = 0; j < 2; j++) {
                    mma16816(acc[i][j], ah, wh0[j][kb], wh1[j][kb]);   // hi*hi
                    mma16816(acc[i][j], ah, wl0[j][kb], wl1[j][kb]);   // hi*lo
                    mma16816(acc[i][j], al, wh0[j][kb], wh1[j][kb]);   // lo*hi
                }
            }
            #pragma unroll
            for (int kb = 0; kb < 2; kb++) {
                uint4 ah = Ab[(8 + kb) * 32];
                uint4 al = Ab[(10 + kb) * 32];
                #pragma unroll
                for (int j = 0; j < 2; j++) {
                    mma16816(acc[i][j], ah, vh0[j][kb], vh1[j][kb]);
                    mma16816(acc[i][j], ah, vl0[j][kb], vl1[j][kb]);
                    mma16816(acc[i][j], al, vh0[j][kb], vh1[j][kb]);
                }
            }
        }

        // ---- epilogue: relu(acc + P[src] + Q[dst]) ----
        #pragma unroll
        for (int i = 0; i < 4; i++) {
            const int mt = wm * 4 + i;
            int r1 = mt * 16 + lr, r2 = r1 + 8;
            int e1 = base + r1, e2 = base + r2;
            int s1 = srcs[r1], d1 = dsts[r1];
            int s2 = srcs[r2], d2 = dsts[r2];
            #pragma unroll
            for (int j = 0; j < 2; j++) {
                const int c = wn * 16 + j * 8 + lc * 2;
                if (e1 < n_edges) {
                    float2 p = *(const float2*)(g_P + (size_t)s1 * HID + c);
                    float2 q = *(const float2*)(g_Q + (size_t)d1 * HID + c);
                    float2 o;
                    o.x = fmaxf(acc[i][j][0] + p.x + q.x, 0.f);
                    o.y = fmaxf(acc[i][j][1] + p.y + q.y, 0.f);
                    *(float2*)(out + (size_t)e1 * HID + c) = o;
                }
                if (e2 < n_edges) {
                    float2 p = *(const float2*)(g_P + (size_t)s2 * HID + c);
                    float2 q = *(const float2*)(g_Q + (size_t)d2 * HID + c);
                    float2 o;
                    o.x = fmaxf(acc[i][j][2] + p.x + q.x, 0.f);
                    o.y = fmaxf(acc[i][j][3] + p.y + q.y, 0.f);
                    *(float2*)(out + (size_t)e2 * HID + c) = o;
                }
            }
        }
    }
}

// ---------------------------------------------------------------------------
extern "C" void kernel_launch(void* const* d_in, const int* in_sizes, int n_in,
                              void* d_out, int out_size)
{
    const float* h   = (const float*)d_in[0];
    const float* e_h = (const float*)d_in[1];
    const float* ext = (const float*)d_in[2];
    const float* W1  = (const float*)d_in[3];
    const float* b1  = (const float*)d_in[4];
    const float* W2  = (const float*)d_in[5];
    const float* b2  = (const float*)d_in[6];
    const int*   src = (const int*)d_in[7];
    const int*   dst = (const int*)d_in[8];
    float* out = (float*)d_out;

    int n_nodes = in_sizes[0] / HID;
    int n_edges = in_sizes[7];

    cudaFuncSetAttribute(node_pre, cudaFuncAttributeMaxDynamicSharedMemorySize,
                         NODE_SMEM_BYTES);
    cudaFuncSetAttribute(edge_kernel, cudaFuncAttributeMaxDynamicSharedMemorySize,
                         EDGE_SMEM_BYTES);

    combo_kernel<<<49, 256>>>(W1, b1, W2, b2);
    build_B<<<12, 256>>>(W2);

    int node_tiles = (n_nodes + TN - 1) / TN;
    int grid1 = node_tiles < 592 ? node_tiles : 592;
    node_pre<<<grid1, 256, NODE_SMEM_BYTES>>>(h, n_nodes);

    int edge_tiles = (n_edges + TM - 1) / TM;
    int grid2 = edge_tiles < 444 ? edge_tiles : 444;
    edge_kernel<<<grid2, 256, EDGE_SMEM_BYTES>>>(e_h, ext, src, dst, out, n_edges);
}

// round 15
// speedup vs baseline: 1.4806x; 1.4806x over previous
#include <cuda_runtime.h>
#include <cstdint>

#define HID 64
#define EXT 32
#define TN 64
#define TM 128          // edges per tile
#define MAX_NODES 50000

// ---------------------------------------------------------------------------
// Globals
// ---------------------------------------------------------------------------
__device__ float g_P[MAX_NODES * HID];        // h @ (W1a@W2a)
__device__ float g_Q[MAX_NODES * HID];        // h @ (W1c@W2a) + b12 (bias baked in)
__device__ float g_W12[HID * HID];            // W1b @ W2a (fp32)
__device__ float g_Wa2[HID * HID];
__device__ float g_Wc2[HID * HID];
__device__ float g_b12[HID];                  // b1 @ W2a + b2
// Split bf16 weights, packed as bf16x2 per k-pair: g_Bp[kp][n], kp = k/2.
// kp [0:32)=W12_hi [32:64)=W12_lo [64:80)=W2b_hi [80:96)=W2b_lo
__device__ unsigned g_Bp[96 * 64];

typedef unsigned long long u64;

// Single extern shared declaration for all kernels
extern __shared__ __align__(16) unsigned char smraw[];

// ---------------------------------------------------------------------------
// Helpers
// ---------------------------------------------------------------------------
__device__ __forceinline__ u64 pk2(float x, float y) {
    u64 r; asm("mov.b64 %0,{%1,%2};" : "=l"(r) : "f"(x), "f"(y)); return r;
}
__device__ __forceinline__ float2 up2(u64 v) {
    float2 f; asm("mov.b64 {%0,%1},%2;" : "=f"(f.x), "=f"(f.y) : "l"(v)); return f;
}
__device__ __forceinline__ void ffma2(u64& d, u64 a, u64 b) {
    asm("fma.rn.f32x2 %0,%1,%2,%0;" : "+l"(d) : "l"(a), "l"(b));
}
// bf16 hi/lo split of two floats, packed as bf16x2 words (x0 -> low half)
__device__ __forceinline__ void split2(float x0, float x1, unsigned& hi, unsigned& lo) {
    unsigned h;
    asm("cvt.rn.bf16x2.f32 %0, %1, %2;" : "=r"(h) : "f"(x1), "f"(x0));
    float h0 = __uint_as_float(h << 16);
    float h1 = __uint_as_float(h & 0xFFFF0000u);
    float l0 = x0 - h0, l1 = x1 - h1;
    unsigned l;
    asm("cvt.rn.bf16x2.f32 %0, %1, %2;" : "=r"(l) : "f"(l1), "f"(l0));
    hi = h; lo = l;
}
__device__ __forceinline__ void mma16816(float* c, uint4 a, unsigned b0, unsigned b1) {
    asm volatile(
        "mma.sync.aligned.m16n8k16.row.col.f32.bf16.bf16.f32 "
        "{%0,%1,%2,%3},{%4,%5,%6,%7},{%8,%9},{%0,%1,%2,%3};"
        : "+f"(c[0]), "+f"(c[1]), "+f"(c[2]), "+f"(c[3])
        : "r"(a.x), "r"(a.y), "r"(a.z), "r"(a.w), "r"(b0), "r"(b1));
}

// Fragment-linear A smem address for element (row r, k-pair kp).
// Frag block (mt,kt) is 32 lanes x 16B; within 16B: regs a0..a3.
__device__ __forceinline__ unsigned frag_addr(int r, int kp) {
    int mt = r >> 4, rr = r & 15;
    int kt = kp >> 3, kk = kp & 7;
    int lane = ((rr & 7) << 2) + (kk & 3);
    int reg  = (rr >> 3) + ((kk >> 2) << 1);
    return (unsigned)(((((mt * 12 + kt) << 5) + lane) << 4) + (reg << 2));
}

// ---------------------------------------------------------------------------
// Kernel 0a: fold W2a into W1 parts + bias.  grid 49 x 256
// ---------------------------------------------------------------------------
__global__ __launch_bounds__(256) void combo_kernel(
    const float* __restrict__ W1, const float* __restrict__ b1,
    const float* __restrict__ W2, const float* __restrict__ b2)
{
    __shared__ float W2s[HID * HID];
    __shared__ float rW[256];
    for (int i = threadIdx.x; i < HID * HID; i += 256) W2s[i] = W2[i];

    int b = blockIdx.x;
    if (b < 48) {
        int mat = b >> 4, rb = b & 15;
        rW[threadIdx.x] = W1[(size_t)mat * HID * HID + rb * 256 + threadIdx.x];
        __syncthreads();
        int lr = threadIdx.x >> 6, col = threadIdx.x & 63;
        float acc = 0.f;
        #pragma unroll 8
        for (int k = 0; k < HID; k++)
            acc = fmaf(rW[lr * HID + k], W2s[k * HID + col], acc);
        float* dstW = (mat == 0) ? g_Wa2 : (mat == 1) ? g_W12 : g_Wc2;
        dstW[(rb * 4 + lr) * HID + col] = acc;
    } else {
        __syncthreads();
        if (threadIdx.x < HID) {
            float acc = b2[threadIdx.x];
            #pragma unroll 8
            for (int k = 0; k < HID; k++)
                acc = fmaf(b1[k], W2s[k * HID + threadIdx.x], acc);
            g_b12[threadIdx.x] = acc;
        }
    }
}

// ---------------------------------------------------------------------------
// Kernel 0b: build split bf16x2 weight blob.  grid 12 x 256
// ---------------------------------------------------------------------------
__global__ __launch_bounds__(256) void build_B(const float* __restrict__ W2)
{
    int idx = blockIdx.x * 256 + threadIdx.x;
    if (idx < 48 * 64) {
        int kp = idx >> 6, n = idx & 63;
        float x0, x1;
        int hi_kp, lo_kp;
        if (kp < 32) {
            x0 = g_W12[(2 * kp) * HID + n];
            x1 = g_W12[(2 * kp + 1) * HID + n];
            hi_kp = kp; lo_kp = 32 + kp;
        } else {
            int ks = kp - 32;
            x0 = W2[(size_t)(HID + 2 * ks) * HID + n];
            x1 = W2[(size_t)(HID + 2 * ks + 1) * HID + n];
            hi_kp = 64 + ks; lo_kp = 80 + ks;
        }
        unsigned hi, lo;
        split2(x0, x1, hi, lo);
        g_Bp[hi_kp * 64 + n] = hi;
        g_Bp[lo_kp * 64 + n] = lo;
    }
}

// ---------------------------------------------------------------------------
// Kernel 1: per-node  P = h @ Wa2 ; Q = h @ Wc2 + b12   (FFMA2)
// ---------------------------------------------------------------------------
#define NODE_SMEM_BYTES ((4096 + 4096 + HID * TN) * 4)

__global__ __launch_bounds__(256) void node_pre(const float* __restrict__ h,
                                                int n_nodes)
{
    float* sm  = (float*)smraw;
    float* Wa  = sm;
    float* Wc  = Wa + 4096;
    float* hst = Wc + 4096;

    for (int i = threadIdx.x; i < HID * HID; i += 256) {
        Wa[i] = g_Wa2[i];
        Wc[i] = g_Wc2[i];
    }

    const int tx = threadIdx.x & 15;
    const int ty = threadIdx.x >> 4;
    const int j0 = tx * 4;
    const int r0 = ty * 4;
    const int ntiles = (n_nodes + TN - 1) / TN;

    float4 bv = *(const float4*)(g_b12 + j0);
    u64 qb0 = pk2(bv.x, bv.x), qb1 = pk2(bv.y, bv.y),
        qb2 = pk2(bv.z, bv.z), qb3 = pk2(bv.w, bv.w);

    for (int tile = blockIdx.x; tile < ntiles; tile += gridDim.x) {
        const int base = tile * TN;
        __syncthreads();
        for (int idx = threadIdx.x; idx < (HID / 4) * TN; idx += 256) {
            int cq = idx >> 6;
            int r  = idx & (TN - 1);
            int node = base + r;
            float4 v = make_float4(0.f, 0.f, 0.f, 0.f);
            if (node < n_nodes) v = *(const float4*)(h + (size_t)node * HID + cq * 4);
            hst[(cq * 4 + 0) * TN + r] = v.x;
            hst[(cq * 4 + 1) * TN + r] = v.y;
            hst[(cq * 4 + 2) * TN + r] = v.z;
            hst[(cq * 4 + 3) * TN + r] = v.w;
        }
        __syncthreads();

        u64 aP[4][2], aQ[4][2];
        #pragma unroll
        for (int j = 0; j < 4; j++) aP[j][0] = aP[j][1] = 0ULL;
        aQ[0][0] = aQ[0][1] = qb0;
        aQ[1][0] = aQ[1][1] = qb1;
        aQ[2][0] = aQ[2][1] = qb2;
        aQ[3][0] = aQ[3][1] = qb3;

        #pragma unroll 4
        for (int k = 0; k < HID; k++) {
            ulonglong2 sv = *(const ulonglong2*)(hst + k * TN + r0);
            float4 wa = *(const float4*)(Wa + k * HID + j0);
            float4 wc = *(const float4*)(Wc + k * HID + j0);
            u64 a0 = pk2(wa.x, wa.x), a1 = pk2(wa.y, wa.y),
                a2 = pk2(wa.z, wa.z), a3 = pk2(wa.w, wa.w);
            u64 c0 = pk2(wc.x, wc.x), c1 = pk2(wc.y, wc.y),
                c2 = pk2(wc.z, wc.z), c3 = pk2(wc.w, wc.w);
            ffma2(aP[0][0], a0, sv.x); ffma2(aP[0][1], a0, sv.y);
            ffma2(aP[1][0], a1, sv.x); ffma2(aP[1][1], a1, sv.y);
            ffma2(aP[2][0], a2, sv.x); ffma2(aP[2][1], a2, sv.y);
            ffma2(aP[3][0], a3, sv.x); ffma2(aP[3][1], a3, sv.y);
            ffma2(aQ[0][0], c0, sv.x); ffma2(aQ[0][1], c0, sv.y);
            ffma2(aQ[1][0], c1, sv.x); ffma2(aQ[1][1], c1, sv.y);
            ffma2(aQ[2][0], c2, sv.x); ffma2(aQ[2][1], c2, sv.y);
            ffma2(aQ[3][0], c3, sv.x); ffma2(aQ[3][1], c3, sv.y);
        }
        #pragma unroll
        for (int r = 0; r < 4; r++) {
            int node = base + r0 + r;
            if (node < n_nodes) {
                float4 p, q; float2 c;
                c = up2(aP[0][r >> 1]); p.x = (r & 1) ? c.y : c.x;
                c = up2(aP[1][r >> 1]); p.y = (r & 1) ? c.y : c.x;
                c = up2(aP[2][r >> 1]); p.z = (r & 1) ? c.y : c.x;
                c = up2(aP[3][r >> 1]); p.w = (r & 1) ? c.y : c.x;
                c = up2(aQ[0][r >> 1]); q.x = (r & 1) ? c.y : c.x;
                c = up2(aQ[1][r >> 1]); q.y = (r & 1) ? c.y : c.x;
                c = up2(aQ[2][r >> 1]); q.z = (r & 1) ? c.y : c.x;
                c = up2(aQ[3][r >> 1]); q.w = (r & 1) ? c.y : c.x;
                *(float4*)(g_P + (size_t)node * HID + j0) = p;
                *(float4*)(g_Q + (size_t)node * HID + j0) = q;
            }
        }
    }
}

// ---------------------------------------------------------------------------
// Kernel 2: per-edge via mma.sync — R9 layout, occupancy-tuned.
//   A kt blocks: 0-3 eh_hi | 4-7 eh_lo | 8-9 ext_hi | 10-11 ext_lo
//   Per (mt, kb<4): ah x W12_hi, ah x W12_lo, al x W12_hi
//   Per (mt, kb<2): ah x W2b_hi, ah x W2b_lo, al x W2b_hi
//   Consumer split into two 4-mt halves (acc live range 16 regs, not 32).
//   out = relu( sum + P[src] + Q[dst] )
// ---------------------------------------------------------------------------
#define A_BYTES (8 * 12 * 32 * 16)      // 49152
#define OFF_SRC A_BYTES
#define OFF_DST (OFF_SRC + TM * 4)
#define EDGE_SMEM_BYTES (OFF_DST + TM * 4)

__global__ __launch_bounds__(256, 4) void edge_kernel(
    const float* __restrict__ e_h,
    const float* __restrict__ ext,
    const int* __restrict__ src,
    const int* __restrict__ dst,
    float* __restrict__ out,
    int n_edges)
{
    unsigned char* A = smraw;
    int* srcs = (int*)(smraw + OFF_SRC);
    int* dsts = (int*)(smraw + OFF_DST);

    const int tid = threadIdx.x;
    const int w = tid >> 5, lane = tid & 31;
    const int n0 = w * 8;
    const int lr = lane >> 2;            // 0..7
    const int lc = lane & 3;             // 0..3

    // ---- B fragments, fully deduplicated: 24 words total ----
    unsigned wh0[4], wh1[4], wl0[4], wl1[4];   // W12 hi/lo
    unsigned vh0[2], vh1[2], vl0[2], vl1[2];   // W2b hi/lo
    #pragma unroll
    for (int kb = 0; kb < 4; kb++) {
        int kp = kb * 8 + lc;
        wh0[kb] = g_Bp[kp * 64 + n0 + lr];
        wh1[kb] = g_Bp[(kp + 4) * 64 + n0 + lr];
        wl0[kb] = g_Bp[(32 + kp) * 64 + n0 + lr];
        wl1[kb] = g_Bp[(32 + kp + 4) * 64 + n0 + lr];
    }
    #pragma unroll
    for (int kb = 0; kb < 2; kb++) {
        int kp = 64 + kb * 8 + lc;
        vh0[kb] = g_Bp[kp * 64 + n0 + lr];
        vh1[kb] = g_Bp[(kp + 4) * 64 + n0 + lr];
        vl0[kb] = g_Bp[(kp + 16) * 64 + n0 + lr];
        vl1[kb] = g_Bp[(kp + 16 + 4) * 64 + n0 + lr];
    }

    const int ntiles = (n_edges + TM - 1) / TM;

    for (int tile = blockIdx.x; tile < ntiles; tile += gridDim.x) {
        const int base = tile * TM;
        __syncthreads();   // previous tile fully consumed before A overwrite

        // ---- stage e_h (R9 producer): hi -> kt 0-3, lo -> kt 4-7 ----
        for (int idx = tid; idx < TM * 16; idx += 256) {
            int r = idx >> 4, c4 = (idx & 15) << 2;
            int e = base + r;
            float4 v = (e < n_edges) ? *(const float4*)(e_h + (size_t)e * HID + c4)
                                     : make_float4(0.f, 0.f, 0.f, 0.f);
            unsigned h01, l01, h23, l23;
            split2(v.x, v.y, h01, l01);
            split2(v.z, v.w, h23, l23);
            int kp = c4 >> 1;
            *(unsigned*)(A + frag_addr(r, kp))          = h01;
            *(unsigned*)(A + frag_addr(r, kp + 1))      = h23;
            *(unsigned*)(A + frag_addr(r, 32 + kp))     = l01;
            *(unsigned*)(A + frag_addr(r, 32 + kp + 1)) = l23;
        }
        // ---- stage ext: hi -> kt 8-9, lo -> kt 10-11 ----
        for (int idx = tid; idx < TM * 8; idx += 256) {
            int r = idx >> 3, c4 = (idx & 7) << 2;
            int e = base + r;
            float4 v = (e < n_edges) ? *(const float4*)(ext + (size_t)e * EXT + c4)
                                     : make_float4(0.f, 0.f, 0.f, 0.f);
            unsigned h01, l01, h23, l23;
            split2(v.x, v.y, h01, l01);
            split2(v.z, v.w, h23, l23);
            int kp = c4 >> 1;
            *(unsigned*)(A + frag_addr(r, 64 + kp))     = h01;
            *(unsigned*)(A + frag_addr(r, 64 + kp + 1)) = h23;
            *(unsigned*)(A + frag_addr(r, 80 + kp))     = l01;
            *(unsigned*)(A + frag_addr(r, 80 + kp + 1)) = l23;
        }
        if (tid < TM) {
            int e = base + tid;
            srcs[tid] = (e < n_edges) ? src[e] : 0;
            dsts[tid] = (e < n_edges) ? dst[e] : 0;
        }
        __syncthreads();

        // ---- two halves of 4 m-tiles each: MMA then epilogue (acc live = 16) ----
        const int c = n0 + lc * 2;
        #pragma unroll
        for (int half = 0; half < 2; half++) {
            float acc[4][4];
            #pragma unroll
            for (int i = 0; i < 4; i++) {
                acc[i][0] = acc[i][1] = acc[i][2] = acc[i][3] = 0.f;
                const int mt = half * 4 + i;
                const uint4* Ab = (const uint4*)(A) + (mt * 12) * 32 + lane;
                #pragma unroll
                for (int kb = 0; kb < 4; kb++) {
                    uint4 ah = Ab[kb * 32];
                    uint4 al = Ab[(4 + kb) * 32];
                    mma16816(acc[i], ah, wh0[kb], wh1[kb]);   // hi*hi
                    mma16816(acc[i], ah, wl0[kb], wl1[kb]);   // hi*lo
                    mma16816(acc[i], al, wh0[kb], wh1[kb]);   // lo*hi
                }
                #pragma unroll
                for (int kb = 0; kb < 2; kb++) {
                    uint4 ah = Ab[(8 + kb) * 32];
                    uint4 al = Ab[(10 + kb) * 32];
                    mma16816(acc[i], ah, vh0[kb], vh1[kb]);
                    mma16816(acc[i], ah, vl0[kb], vl1[kb]);
                    mma16816(acc[i], al, vh0[kb], vh1[kb]);
                }
            }
            // epilogue for this half
            #pragma unroll
            for (int i = 0; i < 4; i++) {
                const int mt = half * 4 + i;
                int r1 = mt * 16 + lr, r2 = r1 + 8;
                int e1 = base + r1, e2 = base + r2;
                if (e1 < n_edges) {
                    float2 p = *(const float2*)(g_P + (size_t)srcs[r1] * HID + c);
                    float2 q = *(const float2*)(g_Q + (size_t)dsts[r1] * HID + c);
                    float2 o;
                    o.x = fmaxf(acc[i][0] + p.x + q.x, 0.f);
                    o.y = fmaxf(acc[i][1] + p.y + q.y, 0.f);
                    *(float2*)(out + (size_t)e1 * HID + c) = o;
                }
                if (e2 < n_edges) {
                    float2 p = *(const float2*)(g_P + (size_t)srcs[r2] * HID + c);
                    float2 q = *(const float2*)(g_Q + (size_t)dsts[r2] * HID + c);
                    float2 o;
                    o.x = fmaxf(acc[i][2] + p.x + q.x, 0.f);
                    o.y = fmaxf(acc[i][3] + p.y + q.y, 0.f);
                    *(float2*)(out + (size_t)e2 * HID + c) = o;
                }
            }
        }
    }
}

// ---------------------------------------------------------------------------
extern "C" void kernel_launch(void* const* d_in, const int* in_sizes, int n_in,
                              void* d_out, int out_size)
{
    const float* h   = (const float*)d_in[0];
    const float* e_h = (const float*)d_in[1];
    const float* ext = (const float*)d_in[2];
    const float* W1  = (const float*)d_in[3];
    const float* b1  = (const float*)d_in[4];
    const float* W2  = (const float*)d_in[5];
    const float* b2  = (const float*)d_in[6];
    const int*   src = (const int*)d_in[7];
    const int*   dst = (const int*)d_in[8];
    float* out = (float*)d_out;

    int n_nodes = in_sizes[0] / HID;
    int n_edges = in_sizes[7];

    cudaFuncSetAttribute(node_pre, cudaFuncAttributeMaxDynamicSharedMemorySize,
                         NODE_SMEM_BYTES);
    cudaFuncSetAttribute(edge_kernel, cudaFuncAttributeMaxDynamicSharedMemorySize,
                         EDGE_SMEM_BYTES);

    combo_kernel<<<49, 256>>>(W1, b1, W2, b2);
    build_B<<<12, 256>>>(W2);

    int node_tiles = (n_nodes + TN - 1) / TN;
    int grid1 = node_tiles < 592 ? node_tiles : 592;
    node_pre<<<grid1, 256, NODE_SMEM_BYTES>>>(h, n_nodes);

    int edge_tiles = (n_edges + TM - 1) / TM;
    int grid2 = edge_tiles < 592 ? edge_tiles : 592;
    edge_kernel<<<grid2, 256, EDGE_SMEM_BYTES>>>(e_h, ext, src, dst, out, n_edges);
}